// round 8
// baseline (speedup 1.0000x reference)
#include <cuda_runtime.h>
#include <cuda_bf16.h>

// FINAL. The reference network mathematically collapses: the GNN "layernorm"
// is over a feature axis of size 1, so (y - mean)/sqrt(var+eps) == 0 exactly
// and h == ln_bias[l] after each propagation layer, independent of everything
// upstream (hash grids, SIREN trunk, member heads, all 2M graph edges).
// Output = softplus(ln_bias[1,0]) * sigmoid((1 - psi_n) * 50), elementwise.
//
// Saturation established over R1-R7: kernel-internal time invariant at
// ~4.1-4.4us across every body variant (IEEE expf / tanhf / __expf) and every
// grid shape — all ncu pipes ~0%, DRAM 0.8%, issue 3.4%. The duration IS the
// launch (T_ovh ~5000cyc + one DRAM round-trip). Bench results by shape:
//   64x256: 6.9 | 128x128: 4.58-4.61 | 256x64: 4.51-4.58 | 512x32: 4.61
// 256 CTAs x 64 thr is the best-measured point; this file pins it.

__global__ __launch_bounds__(64, 32)
void collapsed_forward_kernel(const float* __restrict__ psi_n,
                              const float* __restrict__ ln_bias,
                              float* __restrict__ out) {
    int i = blockIdx.x * 64 + threadIdx.x;   // exactly 16384 threads = n/4

    // Issue both loads immediately so their DRAM latencies overlap.
    float4 p = reinterpret_cast<const float4*>(psi_n)[i];
    float b = __ldg(&ln_bias[1]);

    float refined = __logf(1.0f + __expf(b));   // softplus(ln_bias[1])

    // refined * sigmoid((1-p)*50); sigmoid arg negated: (p-1)*50 = fma(p,50,-50)
    float4 r;
    r.x = __fdividef(refined, 1.0f + __expf(fmaf(p.x, 50.0f, -50.0f)));
    r.y = __fdividef(refined, 1.0f + __expf(fmaf(p.y, 50.0f, -50.0f)));
    r.z = __fdividef(refined, 1.0f + __expf(fmaf(p.z, 50.0f, -50.0f)));
    r.w = __fdividef(refined, 1.0f + __expf(fmaf(p.w, 50.0f, -50.0f)));
    reinterpret_cast<float4*>(out)[i] = r;
}

extern "C" void kernel_launch(void* const* d_in, const int* in_sizes, int n_in,
                              void* d_out, int out_size) {
    const float* psi_n   = (const float*)d_in[2];
    const float* ln_bias = (const float*)d_in[25];
    float* out = (float*)d_out;

    int n4 = out_size / 4;          // 16384
    int blocks = n4 / 64;           // 256 CTAs x 64 threads, exact cover
    collapsed_forward_kernel<<<blocks, 64>>>(psi_n, ln_bias, out);
}

// round 9
// speedup vs baseline: 1.0141x; 1.0141x over previous
#include <cuda_runtime.h>
#include <cuda_bf16.h>

// FINAL (held). The reference network mathematically collapses: the GNN
// "layernorm" is over a feature axis of size 1, so (y-mean)/sqrt(var+eps)==0
// exactly and h == ln_bias[l] after each propagation layer, independent of
// everything upstream (hash grids, SIREN trunk, member heads, 2M graph edges).
// Output = softplus(ln_bias[1,0]) * sigmoid((1 - psi_n) * 50), elementwise.
//
// Saturation established R1-R8. Kernel-internal time ~4.1us invariant across
// every body/grid variant; all ncu pipes ~0% — the duration is launch
// overhead (T_ovh ~5000cyc + one DRAM round-trip). Byte-identical source
// benched three times: 4.512 / 4.576 / 4.608 us — harness noise is +/-0.05us,
// larger than any remaining lever. Configuration space characterized:
//   64x256: 6.9 | 128x128: 4.58-4.61 | 256x64: 4.51-4.61 | 512x32: 4.61
// This pins the best-mean point: 256 CTAs x 64 thr, __expf/__fdividef, 16 regs.

__global__ __launch_bounds__(64, 32)
void collapsed_forward_kernel(const float* __restrict__ psi_n,
                              const float* __restrict__ ln_bias,
                              float* __restrict__ out) {
    int i = blockIdx.x * 64 + threadIdx.x;   // exactly 16384 threads = n/4

    // Issue both loads immediately so their DRAM latencies overlap.
    float4 p = reinterpret_cast<const float4*>(psi_n)[i];
    float b = __ldg(&ln_bias[1]);

    float refined = __logf(1.0f + __expf(b));   // softplus(ln_bias[1])

    // refined * sigmoid((1-p)*50); sigmoid arg negated: (p-1)*50 = fma(p,50,-50)
    float4 r;
    r.x = __fdividef(refined, 1.0f + __expf(fmaf(p.x, 50.0f, -50.0f)));
    r.y = __fdividef(refined, 1.0f + __expf(fmaf(p.y, 50.0f, -50.0f)));
    r.z = __fdividef(refined, 1.0f + __expf(fmaf(p.z, 50.0f, -50.0f)));
    r.w = __fdividef(refined, 1.0f + __expf(fmaf(p.w, 50.0f, -50.0f)));
    reinterpret_cast<float4*>(out)[i] = r;
}

extern "C" void kernel_launch(void* const* d_in, const int* in_sizes, int n_in,
                              void* d_out, int out_size) {
    const float* psi_n   = (const float*)d_in[2];
    const float* ln_bias = (const float*)d_in[25];
    float* out = (float*)d_out;

    int n4 = out_size / 4;          // 16384
    int blocks = n4 / 64;           // 256 CTAs x 64 threads, exact cover
    collapsed_forward_kernel<<<blocks, 64>>>(psi_n, ln_bias, out);
}